// round 14
// baseline (speedup 1.0000x reference)
#include <cuda_runtime.h>
#include <cuda_fp16.h>
#include <float.h>
#include <math.h>

#define CN 12288          // CODE_NUM
#define GD 128            // GRAPH
#define HD 128            // HIDDEN
#define AT 64             // ATT
#define KSPLIT 4

// ----------------- scratch (device globals; no allocation allowed) ---------
__device__ float g_GI[CN * 3 * HD]; // x @ W_ih^T + b_ih
__device__ float g_GH[CN * 3 * HD]; // h @ W_hh^T + b_hh
__device__ __half g_Qh[CN * AT];    // Q * 0.125*log2e, fp16 (tail zero)
__device__ __half g_Kh[CN * AT];    // K, fp16  (tail zero)
__device__ __half g_VT[HD * CN];    // V transposed [d][slot], fp16 (tail zero)
__device__ float g_O3[KSPLIT * CN * HD];  // per-split O partials
__device__ float g_L3[KSPLIT * CN];       // per-split l partials
__device__ int   g_idx1[CN];
__device__ int   g_idx23[CN];       // row | (m2 << 30)
__device__ int   g_cnt[2] = {0, 0}; // [0]=n1, [1]=n23 (reset by k_final)
__device__ int   g_done[CN / 64];   // per-q-tile split counters (self-resetting)
__device__ unsigned g_outacc[HD];   // ordered-uint float max accumulator
__device__ float g_tf[HD];          // time features

__device__ __forceinline__ unsigned ford(float f) {
    unsigned u = __float_as_uint(f);
    return (u & 0x80000000u) ? ~u : (u | 0x80000000u);
}
__device__ __forceinline__ float funord(unsigned u) {
    return (u & 0x80000000u) ? __uint_as_float(u ^ 0x80000000u)
                             : __uint_as_float(~u);
}

// round-to-nearest tf32 (for MMA operand staging)
__device__ __forceinline__ float tf32r(float x) {
    unsigned u;
    asm("cvt.rna.tf32.f32 %0, %1;" : "=r"(u) : "f"(x));
    return __uint_as_float(u);
}

// m16n8k8 tf32 MMA, fp32 accumulate (projection GEMMs)
__device__ __forceinline__ void mma_tf32(float* c, const unsigned* a,
                                         unsigned b0, unsigned b1) {
    asm volatile(
        "mma.sync.aligned.m16n8k8.row.col.f32.tf32.tf32.f32 "
        "{%0,%1,%2,%3}, {%4,%5,%6,%7}, {%8,%9}, {%0,%1,%2,%3};"
        : "+f"(c[0]), "+f"(c[1]), "+f"(c[2]), "+f"(c[3])
        : "r"(a[0]), "r"(a[1]), "r"(a[2]), "r"(a[3]), "r"(b0), "r"(b1));
}

// m16n8k16 fp16 MMA, fp32 accumulate (flash)
__device__ __forceinline__ void mma_f16(float* c, const unsigned* a,
                                        unsigned b0, unsigned b1) {
    asm volatile(
        "mma.sync.aligned.m16n8k16.row.col.f32.f16.f16.f32 "
        "{%0,%1,%2,%3}, {%4,%5,%6,%7}, {%8,%9}, {%0,%1,%2,%3};"
        : "+f"(c[0]), "+f"(c[1]), "+f"(c[2]), "+f"(c[3])
        : "r"(a[0]), "r"(a[1]), "r"(a[2]), "r"(a[3]), "r"(b0), "r"(b1));
}

// ldmatrix x4 (native order; our smem tiles already match B-fragment layout)
__device__ __forceinline__ void ldsm4(unsigned& r0, unsigned& r1,
                                      unsigned& r2, unsigned& r3, unsigned addr) {
    asm volatile("ldmatrix.sync.aligned.m8n8.x4.shared.b16 {%0,%1,%2,%3}, [%4];"
                 : "=r"(r0), "=r"(r1), "=r"(r2), "=r"(r3) : "r"(addr));
}

__device__ __forceinline__ unsigned pack_h2(float a, float b) {
    __half2 h = __floats2half2_rn(a, b);
    return *reinterpret_cast<unsigned*>(&h);
}

// raw exp2 (log2e is pre-folded into Q): 1 MUFU, no multiply
__device__ __forceinline__ float ex2(float x) {
    float r;
    asm("ex2.approx.f32 %0, %1;" : "=f"(r) : "f"(x));
    return r;
}

// 16B global->shared async copy
__device__ __forceinline__ void cp16(unsigned dst, const void* src) {
    asm volatile("cp.async.cg.shared.global [%0], [%1], 16;"
                 :: "r"(dst), "l"(src));
}

// ----------------- k_zero: zero h_new region (side stream) -----------------
__global__ void k_zero(float* __restrict__ outH) {
    int i = blockIdx.x * 512 + threadIdx.x;            // 768*512 float4
    reinterpret_cast<float4*>(outH)[i] = make_float4(0.f, 0.f, 0.f, 0.f);
}

// ----------------- k_initA: accumulators, tf, compact ----------------------
__global__ void k_initA(const float* __restrict__ interval,
                        const float* __restrict__ Wt, const float* __restrict__ bt,
                        const int* __restrict__ divided) {
    if (blockIdx.x == 0) {
        int t = threadIdx.x;
        if (t < HD) {
            float xt = 1.0f / logf(interval[0] + 2.7182818284590452f);
            g_tf[t] = tanhf(xt * Wt[t] + bt[t]);
            g_outacc[t] = ford(-FLT_MAX);
        }
    }
    int row = blockIdx.x * 512 + threadIdx.x;          // 24*512 = 12288
    int d0 = divided[row * 3 + 0];
    int d1 = divided[row * 3 + 1];
    int d2 = divided[row * 3 + 2];
    if (d0 > 0) {
        int pos = atomicAdd(&g_cnt[0], 1);
        g_idx1[pos] = row;
    }
    if (d1 > 0 || d2 > 0) {
        int pos = atomicAdd(&g_cnt[1], 1);
        g_idx23[pos] = row | ((d1 > 0) ? (1 << 30) : 0);
    }
}

// ----------------- shared GEMM mma part (after smem staging) ---------------
#define GEMM_SMEM (2 * 64 * 132 * 4)
__device__ __forceinline__ void gemm_mma(const float* sm, float c[4][4]) {
    const float* As = sm;              // [64][132]
    const float* Ws = sm + 64 * 132;   // [64][132]
    int t = threadIdx.x;
    int w = t >> 5, lane = t & 31;
    int g = lane >> 2, tid = lane & 3;
    int mw = w >> 1, nw = w & 1;
#pragma unroll
    for (int nt = 0; nt < 4; nt++)
#pragma unroll
        for (int i = 0; i < 4; i++) c[nt][i] = 0.f;
    const float* r0p = As + (16 * mw + g) * 132;
    const float* r8p = r0p + 8 * 132;
#pragma unroll
    for (int ks = 0; ks < 16; ks++) {
        unsigned a[4];
        a[0] = __float_as_uint(r0p[8 * ks + tid]);
        a[1] = __float_as_uint(r8p[8 * ks + tid]);
        a[2] = __float_as_uint(r0p[8 * ks + tid + 4]);
        a[3] = __float_as_uint(r8p[8 * ks + tid + 4]);
#pragma unroll
        for (int nt = 0; nt < 4; nt++) {
            const float* kr = Ws + (nw * 32 + 8 * nt + g) * 132;
            unsigned b0 = __float_as_uint(kr[8 * ks + tid]);
            unsigned b1 = __float_as_uint(kr[8 * ks + tid + 4]);
            mma_tf32(c[nt], a, b0, b1);
        }
    }
}

// W staging helper (direct, tf32-rounded)
__device__ __forceinline__ void stage_W(float* Ws, const float* __restrict__ W,
                                        int col0) {
    int t = threadIdx.x;
    for (int i4 = t; i4 < 64 * 32; i4 += 256) {
        int cc = i4 >> 5, k4 = i4 & 31;
        float4 v = reinterpret_cast<const float4*>(W + (size_t)(col0 + cc) * 128)[k4];
        v.x = tf32r(v.x); v.y = tf32r(v.y); v.z = tf32r(v.z); v.w = tf32r(v.w);
        *reinterpret_cast<float4*>(Ws + cc * 132 + k4 * 4) = v;
    }
}

// GI/GH with fused m1 gather: y 0..5 -> GI (A=co[idx1]); y 6..11 -> GH (A=hid[idx1])
__global__ void __launch_bounds__(256, 2) k_gemm_g(
        const float* __restrict__ co,  const float* __restrict__ hid,
        const float* __restrict__ Wih, const float* __restrict__ Whh,
        const float* __restrict__ bih, const float* __restrict__ bhh) {
    int y = blockIdx.y;
    const float* A = (y < 6) ? co : hid;
    const float* W = (y < 6) ? Wih : Whh;
    const float* bias = (y < 6) ? bih : bhh;
    float* C = (y < 6) ? g_GI : g_GH;
    int M = g_cnt[0];
    int col0 = (y % 6) * 64;
    int row0 = blockIdx.x * 64;
    if (row0 >= M) return;
    extern __shared__ float sm[];
    int t = threadIdx.x;
    for (int i4 = t; i4 < 64 * 32; i4 += 256) {
        int r = i4 >> 5, k4 = i4 & 31;
        float4 v = make_float4(0.f, 0.f, 0.f, 0.f);
        int s = row0 + r;
        if (s < M) {
            int row = g_idx1[s];
            v = reinterpret_cast<const float4*>(A + (size_t)row * 128)[k4];
        }
        v.x = tf32r(v.x); v.y = tf32r(v.y); v.z = tf32r(v.z); v.w = tf32r(v.w);
        *reinterpret_cast<float4*>(sm + r * 132 + k4 * 4) = v;
    }
    stage_W(sm + 64 * 132, W, col0);
    __syncthreads();
    float c[4][4];
    gemm_mma(sm, c);
    int w = t >> 5, lane = t & 31;
    int g = lane >> 2, tid = lane & 3;
    int mw = w >> 1, nw = w & 1;
    int ra = row0 + 16 * mw + g, rb = ra + 8;
#pragma unroll
    for (int nt = 0; nt < 4; nt++) {
        int cb = col0 + nw * 32 + 8 * nt + 2 * tid;
        float2 bz = *reinterpret_cast<const float2*>(bias + cb);
        if (ra < M)
            *reinterpret_cast<float2*>(C + (size_t)ra * 384 + cb) =
                make_float2(c[nt][0] + bz.x, c[nt][1] + bz.y);
        if (rb < M)
            *reinterpret_cast<float2*>(C + (size_t)rb * 384 + cb) =
                make_float2(c[nt][2] + bz.x, c[nt][3] + bz.y);
    }
}

// QKV with fused m23 gather: y=0 Q (A = no_/un per m2 bit, x 0.125*log2e),
// y=1 K (A=co), y=2,3 V halves (A=co; fp16 transposed output)
__global__ void __launch_bounds__(256, 2) k_gemm_qkv(
        const float* __restrict__ co,  const float* __restrict__ no_,
        const float* __restrict__ un,
        const float* __restrict__ Wq,  const float* __restrict__ bq,
        const float* __restrict__ Wk,  const float* __restrict__ bk,
        const float* __restrict__ Wv,  const float* __restrict__ bv) {
    int y = blockIdx.y;
    const float *W, *bias; int col0;
    if (y == 0)      { W = Wq; bias = bq; col0 = 0; }
    else if (y == 1) { W = Wk; bias = bk; col0 = 0; }
    else             { W = Wv; bias = bv; col0 = (y - 2) * 64; }
    int M = g_cnt[1];
    int row0 = blockIdx.x * 64;
    if (row0 >= M) return;
    extern __shared__ float sm[];
    int t = threadIdx.x;
    for (int i4 = t; i4 < 64 * 32; i4 += 256) {
        int r = i4 >> 5, k4 = i4 & 31;
        float4 v = make_float4(0.f, 0.f, 0.f, 0.f);
        int s = row0 + r;
        if (s < M) {
            int e = g_idx23[s];
            int row = e & 0x3FFFFFFF;
            const float* A = (y == 0) ? ((e & (1 << 30)) ? no_ : un) : co;
            v = reinterpret_cast<const float4*>(A + (size_t)row * 128)[k4];
        }
        v.x = tf32r(v.x); v.y = tf32r(v.y); v.z = tf32r(v.z); v.w = tf32r(v.w);
        *reinterpret_cast<float4*>(sm + r * 132 + k4 * 4) = v;
    }
    stage_W(sm + 64 * 132, W, col0);
    __syncthreads();
    float c[4][4];
    gemm_mma(sm, c);
    int w = t >> 5, lane = t & 31;
    int g = lane >> 2, tid = lane & 3;
    int mw = w >> 1, nw = w & 1;
    int ra = row0 + 16 * mw + g, rb = ra + 8;
    if (y <= 1) {
        __half* dst = (y == 0) ? g_Qh : g_Kh;
        float s = (y == 0) ? 0.18033688011112042f : 1.0f;   // 0.125 * log2(e)
#pragma unroll
        for (int nt = 0; nt < 4; nt++) {
            int cb = nw * 32 + 8 * nt + 2 * tid;
            float2 bz = *reinterpret_cast<const float2*>(bias + cb);
            if (ra < M) {
                __half2 h = __floats2half2_rn((c[nt][0] + bz.x) * s, (c[nt][1] + bz.y) * s);
                *reinterpret_cast<__half2*>(dst + (size_t)ra * 64 + cb) = h;
            }
            if (rb < M) {
                __half2 h = __floats2half2_rn((c[nt][2] + bz.x) * s, (c[nt][3] + bz.y) * s);
                *reinterpret_cast<__half2*>(dst + (size_t)rb * 64 + cb) = h;
            }
        }
    } else {
#pragma unroll
        for (int nt = 0; nt < 4; nt++) {
            int cb = col0 + nw * 32 + 8 * nt + 2 * tid;
            float2 bz = *reinterpret_cast<const float2*>(bias + cb);
            if (ra < M) {
                g_VT[(size_t)cb * CN + ra]       = __float2half(c[nt][0] + bz.x);
                g_VT[(size_t)(cb + 1) * CN + ra] = __float2half(c[nt][1] + bz.y);
            }
            if (rb < M) {
                g_VT[(size_t)cb * CN + rb]       = __float2half(c[nt][2] + bz.x);
                g_VT[(size_t)(cb + 1) * CN + rb] = __float2half(c[nt][3] + bz.y);
            }
        }
    }
}

// ----------------- k_flash: fp16 MMA + ldmatrix + cp.async + fused combine -
// Tail keys: K rows = 0 -> S' = 0 -> ex2 = 1 exactly; V rows = 0 so O is
// unaffected; l over-counts by exactly (#invalid keys), subtracted in epilogue.
// Last split-block per q-tile (g_done counter) combines the 4 partials:
// tanh(O/l), scatter to outH, column max. Counter self-resets (replay-safe).
#define FLASH_SMEM ((3 * 64 * 72 + 2 * 128 * 72) * 2)
__global__ void __launch_bounds__(128, 3) k_flash(float* __restrict__ outH) {
    int n23 = g_cnt[1];
    int qb = blockIdx.x / KSPLIT;
    int sp = blockIdx.x % KSPLIT;
    int q0 = qb * 64;
    if (q0 >= n23) return;
    extern __shared__ __half smh[];
    __half* Qs = smh;                              // [64][72]
    int t = threadIdx.x;
    int w = t >> 5, lane = t & 31;
    int g = lane >> 2, tid = lane & 3;
    unsigned lofs = (unsigned)(((lane & 7) * 72 + 8 * (lane >> 3)) * 2);

    int nkb = (n23 + 63) >> 6;
    int chunk = (nkb + KSPLIT - 1) / KSPLIT;
    int kb0 = sp * chunk;
    int kb1 = min(kb0 + chunk, nkb);

    // issue async loads for first K/V tile (stage 0) before staging Q
    {
        int k0 = kb0 << 6;
        __half* Kst = smh + 64 * 72;
        __half* Vst = smh + 3 * 64 * 72;
        for (int i = t; i < 64 * 8; i += 128) {
            int r = i >> 3, c8 = i & 7;
            cp16((unsigned)__cvta_generic_to_shared(Kst + r * 72 + 8 * c8),
                 g_Kh + (size_t)(k0 + r) * AT + 8 * c8);
        }
        for (int i = t; i < 128 * 8; i += 128) {
            int d = i >> 3, j8 = i & 7;
            cp16((unsigned)__cvta_generic_to_shared(Vst + d * 72 + 8 * j8),
                 g_VT + (size_t)d * CN + k0 + 8 * j8);
        }
        asm volatile("cp.async.commit_group;");
    }
    // stage Q tile (overlaps with the async loads above)
    for (int i = t; i < 64 * 8; i += 128) {
        int r = i >> 3, c8 = i & 7;
        *reinterpret_cast<uint4*>(Qs + r * 72 + 8 * c8) =
            *reinterpret_cast<const uint4*>(g_Qh + (size_t)(q0 + r) * AT + 8 * c8);
    }
    __syncthreads();
    // preload Q A-fragments (4 k-chunks of 16)
    unsigned qa[4][4];
    {
        const __half* r0 = Qs + (16 * w + g) * 72;
        const __half* r8 = Qs + (16 * w + g + 8) * 72;
#pragma unroll
        for (int ks = 0; ks < 4; ks++) {
            qa[ks][0] = *reinterpret_cast<const unsigned*>(r0 + 16 * ks + 2 * tid);
            qa[ks][1] = *reinterpret_cast<const unsigned*>(r8 + 16 * ks + 2 * tid);
            qa[ks][2] = *reinterpret_cast<const unsigned*>(r0 + 16 * ks + 2 * tid + 8);
            qa[ks][3] = *reinterpret_cast<const unsigned*>(r8 + 16 * ks + 2 * tid + 8);
        }
    }
    float o[16][4];
#pragma unroll
    for (int nt = 0; nt < 16; nt++)
#pragma unroll
        for (int i = 0; i < 4; i++) o[nt][i] = 0.f;
    float l0 = 0.f, l1 = 0.f;

    for (int kb = kb0; kb < kb1; kb++) {
        int st = (kb - kb0) & 1;
        bool has_next = (kb + 1 < kb1);
        if (has_next) {
            int k0n = (kb + 1) << 6;
            int sn = st ^ 1;
            __half* Kst = smh + (1 + sn) * 64 * 72;
            __half* Vst = smh + 3 * 64 * 72 + sn * 128 * 72;
            for (int i = t; i < 64 * 8; i += 128) {
                int r = i >> 3, c8 = i & 7;
                cp16((unsigned)__cvta_generic_to_shared(Kst + r * 72 + 8 * c8),
                     g_Kh + (size_t)(k0n + r) * AT + 8 * c8);
            }
            for (int i = t; i < 128 * 8; i += 128) {
                int d = i >> 3, j8 = i & 7;
                cp16((unsigned)__cvta_generic_to_shared(Vst + d * 72 + 8 * j8),
                     g_VT + (size_t)d * CN + k0n + 8 * j8);
            }
            asm volatile("cp.async.commit_group;");
            asm volatile("cp.async.wait_group 1;");
        } else {
            asm volatile("cp.async.wait_group 0;");
        }
        __syncthreads();
        unsigned KsA = (unsigned)__cvta_generic_to_shared(smh + (1 + st) * 64 * 72) + lofs;
        unsigned VtA = (unsigned)__cvta_generic_to_shared(smh + 3 * 64 * 72 + st * 128 * 72) + lofs;
        // S = Q K^T : 8 key-tiles, B-fragments via 2 ldmatrix.x4 each
        float c[8][4];
#pragma unroll
        for (int nt = 0; nt < 8; nt++)
#pragma unroll
            for (int i = 0; i < 4; i++) c[nt][i] = 0.f;
#pragma unroll
        for (int nt = 0; nt < 8; nt++) {
            unsigned base = KsA + nt * (8 * 72 * 2);
            unsigned b0, b1, b2, b3;
            ldsm4(b0, b1, b2, b3, base);
            mma_f16(c[nt], qa[0], b0, b1);
            mma_f16(c[nt], qa[1], b2, b3);
            ldsm4(b0, b1, b2, b3, base + 64);
            mma_f16(c[nt], qa[2], b0, b1);
            mma_f16(c[nt], qa[3], b2, b3);
        }
        // P = 2^S' (log2e pre-folded), unmasked; invalid keys give exactly 1
        unsigned pa[4][4];
#pragma unroll
        for (int nt = 0; nt < 8; nt++) {
            float p0 = ex2(c[nt][0]);
            float p1 = ex2(c[nt][1]);
            float p2 = ex2(c[nt][2]);
            float p3 = ex2(c[nt][3]);
            l0 += p0 + p1;
            l1 += p2 + p3;
            int kc = nt >> 1, h = (nt & 1) * 2;
            pa[kc][h]     = pack_h2(p0, p1);
            pa[kc][h + 1] = pack_h2(p2, p3);
        }
        // O += P V : 16 d-tiles, B-fragments via 2 ldmatrix.x4 each
#pragma unroll
        for (int nt = 0; nt < 16; nt++) {
            unsigned base = VtA + nt * (8 * 72 * 2);
            unsigned b0, b1, b2, b3;
            ldsm4(b0, b1, b2, b3, base);
            mma_f16(o[nt], pa[0], b0, b1);
            mma_f16(o[nt], pa[1], b2, b3);
            ldsm4(b0, b1, b2, b3, base + 64);
            mma_f16(o[nt], pa[2], b0, b1);
            mma_f16(o[nt], pa[3], b2, b3);
        }
        __syncthreads();   // all reads of stage st done before its next refill
    }
    // ---- epilogue: store this split's partials ----
    int inv = kb1 * 64 - max(n23, kb0 * 64);
    if (inv < 0) inv = 0;
    l0 += __shfl_xor_sync(0xffffffffu, l0, 1);
    l0 += __shfl_xor_sync(0xffffffffu, l0, 2);
    l1 += __shfl_xor_sync(0xffffffffu, l1, 1);
    l1 += __shfl_xor_sync(0xffffffffu, l1, 2);
    float* lr = reinterpret_cast<float*>(Qs);   // Qs no longer needed
    if (tid == 0) {
        lr[16 * w + g] = l0 - (float)inv;
        lr[16 * w + g + 8] = l1 - (float)inv;
    }
    __syncthreads();
    if (t < 64 && q0 + t < n23)
        g_L3[sp * CN + q0 + t] = lr[t];
    int r0 = q0 + 16 * w + g;
    int r8 = r0 + 8;
    {
        float* base0 = g_O3 + ((size_t)sp * CN + r0) * 128 + 2 * tid;
        float* base8 = g_O3 + ((size_t)sp * CN + r8) * 128 + 2 * tid;
#pragma unroll
        for (int nt = 0; nt < 16; nt++) {
            if (r0 < n23)
                *reinterpret_cast<float2*>(base0 + 8 * nt) = make_float2(o[nt][0], o[nt][1]);
            if (r8 < n23)
                *reinterpret_cast<float2*>(base8 + 8 * nt) = make_float2(o[nt][2], o[nt][3]);
        }
    }
    // ---- fused combine: last split-block of this q-tile does it ----
    __threadfence();
    __shared__ int sLast;
    if (t == 0) {
        int prev = atomicAdd(&g_done[qb], 1);
        sLast = (prev == KSPLIT - 1) ? 1 : 0;
    }
    __syncthreads();
    if (sLast) {
        int c = t;                      // 128 threads -> one column each
        float mx = -FLT_MAX;
        int smax = min(64, n23 - q0);
        for (int k = 0; k < smax; k++) {
            int sl = q0 + k;
            float lt = 0.f, ov = 0.f;
#pragma unroll
            for (int sp2 = 0; sp2 < KSPLIT; sp2++) {
                lt += g_L3[sp2 * CN + sl];
                ov += g_O3[((size_t)sp2 * CN + sl) * 128 + c];
            }
            float h = tanhf(ov / lt);
            int row = g_idx23[sl] & 0x3FFFFFFF;
            outH[(size_t)row * 128 + c] = h;
            mx = fmaxf(mx, h);
        }
        atomicMax(&g_outacc[c], ford(mx));
        if (t == 0) g_done[qb] = 0;     // reset for next graph replay
    }
}

// ----------------- k_gruc: GRU gates + scatter + max (side) ----------------
__global__ void k_gruc(const float* __restrict__ hid, float* __restrict__ outH) {
    int t = threadIdx.x;
    int c = t & 127, sub = t >> 7;
    float mx = -FLT_MAX;
    int n1 = g_cnt[0];
    int s0 = blockIdx.x * 8;
#pragma unroll
    for (int k = 0; k < 4; k++) {
        int s = s0 + sub * 4 + k;
        if (s < n1) {
            int row = g_idx1[s];
            const float* gi = g_GI + (size_t)s * 384;
            const float* gh = g_GH + (size_t)s * 384;
            float r  = 1.f / (1.f + __expf(-(gi[c] + gh[c])));
            float z  = 1.f / (1.f + __expf(-(gi[128 + c] + gh[128 + c])));
            float nn = tanhf(gi[256 + c] + r * gh[256 + c]);
            float h  = hid[(size_t)row * 128 + c];
            float o  = (1.f - z) * nn + z * h;
            outH[(size_t)row * 128 + c] = o;
            mx = fmaxf(mx, o);
        }
    }
    __shared__ float red[2][128];
    red[sub][c] = mx;
    __syncthreads();
    if (t < 128) atomicMax(&g_outacc[t], ford(fmaxf(red[0][t], red[1][t])));
}

// ----------------- k_final: output vector + reset counters for next run ----
__global__ void k_final(float* __restrict__ out) {
    int t = threadIdx.x;
    out[t] = funord(g_outacc[t]) + g_tf[t];
    if (t == 0) { g_cnt[0] = 0; g_cnt[1] = 0; }
}

// ---------------------------------------------------------------------------
extern "C" void kernel_launch(void* const* d_in, const int* in_sizes, int n_in,
                              void* d_out, int out_size) {
    const float* interval = (const float*)d_in[0];
    const float* co   = (const float*)d_in[1];
    const float* no_  = (const float*)d_in[2];
    const float* un   = (const float*)d_in[3];
    const float* hid  = (const float*)d_in[4];
    const int*   divided = (const int*)d_in[5];
    const float* W_ih = (const float*)d_in[6];
    const float* W_hh = (const float*)d_in[7];
    const float* b_ih = (const float*)d_in[8];
    const float* b_hh = (const float*)d_in[9];
    const float* Wq = (const float*)d_in[10];
    const float* bq = (const float*)d_in[11];
    const float* Wk = (const float*)d_in[12];
    const float* bk = (const float*)d_in[13];
    const float* Wv = (const float*)d_in[14];
    const float* bv = (const float*)d_in[15];
    const float* Wt = (const float*)d_in[16];
    const float* bt = (const float*)d_in[17];
    float* out  = (float*)d_out;
    float* outH = out + HD;   // h_new region: [12288, 128] after the 128-vec

    // side stream + fork/join events (created once; identical work every call)
    static cudaStream_t s2 = nullptr;
    static cudaEvent_t e0 = nullptr, e1 = nullptr, ez = nullptr, e3 = nullptr;
    if (s2 == nullptr) {
        cudaStreamCreateWithFlags(&s2, cudaStreamNonBlocking);
        cudaEventCreateWithFlags(&e0, cudaEventDisableTiming);
        cudaEventCreateWithFlags(&e1, cudaEventDisableTiming);
        cudaEventCreateWithFlags(&ez, cudaEventDisableTiming);
        cudaEventCreateWithFlags(&e3, cudaEventDisableTiming);
    }

    cudaFuncSetAttribute(k_gemm_g,   cudaFuncAttributeMaxDynamicSharedMemorySize, GEMM_SMEM);
    cudaFuncSetAttribute(k_gemm_qkv, cudaFuncAttributeMaxDynamicSharedMemorySize, GEMM_SMEM);
    cudaFuncSetAttribute(k_flash,    cudaFuncAttributeMaxDynamicSharedMemorySize, FLASH_SMEM);

    // fork at top: side stream zeroes outH immediately
    cudaEventRecord(e0, 0);
    cudaStreamWaitEvent(s2, e0, 0);
    k_zero<<<768, 512, 0, s2>>>(outH);
    cudaEventRecord(ez, s2);         // outH zero complete (flash writes outH)

    // main: compact, then m23 pipeline (gathers fused into GEMM staging)
    k_initA<<<24, 512>>>(interval, Wt, bt, divided);
    cudaEventRecord(e1, 0);

    // side: after compact -> GI/GH GEMM (fused m1 gather), GRU
    cudaStreamWaitEvent(s2, e1, 0);
    k_gemm_g<<<dim3(192, 12), 256, GEMM_SMEM, s2>>>(co, hid, W_ih, W_hh, b_ih, b_hh);
    k_gruc<<<CN / 8, 256, 0, s2>>>(hid, outH);
    cudaEventRecord(e3, s2);         // gruc done (final may read outacc)

    k_gemm_qkv<<<dim3(192, 4), 256, GEMM_SMEM>>>(co, no_, un,
                                                 Wq, bq, Wk, bk, Wv, bv);
    cudaStreamWaitEvent(0, ez, 0);   // outH zeroed before flash's fused combine
    k_flash<<<(CN / 64) * KSPLIT, 128, FLASH_SMEM>>>(outH);

    cudaStreamWaitEvent(0, e3, 0);
    k_final<<<1, 128>>>(out);
}

// round 17
// speedup vs baseline: 1.2671x; 1.2671x over previous
#include <cuda_runtime.h>
#include <cuda_fp16.h>
#include <float.h>
#include <math.h>

#define CN 12288          // CODE_NUM
#define GD 128            // GRAPH
#define HD 128            // HIDDEN
#define AT 64             // ATT
#define KSPLIT 4

// ----------------- scratch (device globals; no allocation allowed) ---------
__device__ float g_GI[CN * 3 * HD]; // x @ W_ih^T + b_ih
__device__ float g_GH[CN * 3 * HD]; // h @ W_hh^T + b_hh
__device__ __half g_Qh[CN * AT];    // Q * 0.125*log2e, fp16 (tail zero)
__device__ __half g_Kh[CN * AT];    // K, fp16  (tail zero)
__device__ __half g_VT[HD * CN];    // V transposed [d][slot], fp16 (tail zero)
__device__ float g_O3[KSPLIT * CN * HD];  // per-split O partials
__device__ float g_L3[KSPLIT * CN];       // per-split l partials
__device__ int   g_idx1[CN];
__device__ int   g_idx23[CN];       // row | (m2 << 30)
__device__ int   g_cnt[2] = {0, 0}; // [0]=n1, [1]=n23 (reset by k_final)
__device__ unsigned g_outacc[HD];   // ordered-uint float max accumulator
__device__ float g_tf[HD];          // time features

__device__ __forceinline__ unsigned ford(float f) {
    unsigned u = __float_as_uint(f);
    return (u & 0x80000000u) ? ~u : (u | 0x80000000u);
}
__device__ __forceinline__ float funord(unsigned u) {
    return (u & 0x80000000u) ? __uint_as_float(u ^ 0x80000000u)
                             : __uint_as_float(~u);
}

// round-to-nearest tf32 (for MMA operand staging)
__device__ __forceinline__ float tf32r(float x) {
    unsigned u;
    asm("cvt.rna.tf32.f32 %0, %1;" : "=r"(u) : "f"(x));
    return __uint_as_float(u);
}

// m16n8k8 tf32 MMA, fp32 accumulate (projection GEMMs)
__device__ __forceinline__ void mma_tf32(float* c, const unsigned* a,
                                         unsigned b0, unsigned b1) {
    asm volatile(
        "mma.sync.aligned.m16n8k8.row.col.f32.tf32.tf32.f32 "
        "{%0,%1,%2,%3}, {%4,%5,%6,%7}, {%8,%9}, {%0,%1,%2,%3};"
        : "+f"(c[0]), "+f"(c[1]), "+f"(c[2]), "+f"(c[3])
        : "r"(a[0]), "r"(a[1]), "r"(a[2]), "r"(a[3]), "r"(b0), "r"(b1));
}

// m16n8k16 fp16 MMA, fp32 accumulate (flash)
__device__ __forceinline__ void mma_f16(float* c, const unsigned* a,
                                        unsigned b0, unsigned b1) {
    asm volatile(
        "mma.sync.aligned.m16n8k16.row.col.f32.f16.f16.f32 "
        "{%0,%1,%2,%3}, {%4,%5,%6,%7}, {%8,%9}, {%0,%1,%2,%3};"
        : "+f"(c[0]), "+f"(c[1]), "+f"(c[2]), "+f"(c[3])
        : "r"(a[0]), "r"(a[1]), "r"(a[2]), "r"(a[3]), "r"(b0), "r"(b1));
}

// ldmatrix x4 (native order; our smem tiles already match B-fragment layout)
__device__ __forceinline__ void ldsm4(unsigned& r0, unsigned& r1,
                                      unsigned& r2, unsigned& r3, unsigned addr) {
    asm volatile("ldmatrix.sync.aligned.m8n8.x4.shared.b16 {%0,%1,%2,%3}, [%4];"
                 : "=r"(r0), "=r"(r1), "=r"(r2), "=r"(r3) : "r"(addr));
}

__device__ __forceinline__ unsigned pack_h2(float a, float b) {
    __half2 h = __floats2half2_rn(a, b);
    return *reinterpret_cast<unsigned*>(&h);
}

// raw exp2 (log2e is pre-folded into Q): 1 MUFU, no multiply
__device__ __forceinline__ float ex2(float x) {
    float r;
    asm("ex2.approx.f32 %0, %1;" : "=f"(r) : "f"(x));
    return r;
}

// 16B global->shared async copy
__device__ __forceinline__ void cp16(unsigned dst, const void* src) {
    asm volatile("cp.async.cg.shared.global [%0], [%1], 16;"
                 :: "r"(dst), "l"(src));
}

// ----------------- k_zero: zero h_new region (side stream) -----------------
__global__ void k_zero(float* __restrict__ outH) {
    int i = blockIdx.x * 512 + threadIdx.x;            // 768*512 float4
    reinterpret_cast<float4*>(outH)[i] = make_float4(0.f, 0.f, 0.f, 0.f);
}

// ----------------- k_initA: accumulators, tf, compact ----------------------
__global__ void k_initA(const float* __restrict__ interval,
                        const float* __restrict__ Wt, const float* __restrict__ bt,
                        const int* __restrict__ divided) {
    if (blockIdx.x == 0) {
        int t = threadIdx.x;
        if (t < HD) {
            float xt = 1.0f / logf(interval[0] + 2.7182818284590452f);
            g_tf[t] = tanhf(xt * Wt[t] + bt[t]);
            g_outacc[t] = ford(-FLT_MAX);
        }
    }
    int row = blockIdx.x * 512 + threadIdx.x;          // 24*512 = 12288
    int d0 = divided[row * 3 + 0];
    int d1 = divided[row * 3 + 1];
    int d2 = divided[row * 3 + 2];
    if (d0 > 0) {
        int pos = atomicAdd(&g_cnt[0], 1);
        g_idx1[pos] = row;
    }
    if (d1 > 0 || d2 > 0) {
        int pos = atomicAdd(&g_cnt[1], 1);
        g_idx23[pos] = row | ((d1 > 0) ? (1 << 30) : 0);
    }
}

// ----------------- shared GEMM mma part (after smem staging) ---------------
#define GEMM_SMEM (2 * 64 * 132 * 4)
__device__ __forceinline__ void gemm_mma(const float* sm, float c[4][4]) {
    const float* As = sm;              // [64][132]
    const float* Ws = sm + 64 * 132;   // [64][132]
    int t = threadIdx.x;
    int w = t >> 5, lane = t & 31;
    int g = lane >> 2, tid = lane & 3;
    int mw = w >> 1, nw = w & 1;
#pragma unroll
    for (int nt = 0; nt < 4; nt++)
#pragma unroll
        for (int i = 0; i < 4; i++) c[nt][i] = 0.f;
    const float* r0p = As + (16 * mw + g) * 132;
    const float* r8p = r0p + 8 * 132;
#pragma unroll
    for (int ks = 0; ks < 16; ks++) {
        unsigned a[4];
        a[0] = __float_as_uint(r0p[8 * ks + tid]);
        a[1] = __float_as_uint(r8p[8 * ks + tid]);
        a[2] = __float_as_uint(r0p[8 * ks + tid + 4]);
        a[3] = __float_as_uint(r8p[8 * ks + tid + 4]);
#pragma unroll
        for (int nt = 0; nt < 4; nt++) {
            const float* kr = Ws + (nw * 32 + 8 * nt + g) * 132;
            unsigned b0 = __float_as_uint(kr[8 * ks + tid]);
            unsigned b1 = __float_as_uint(kr[8 * ks + tid + 4]);
            mma_tf32(c[nt], a, b0, b1);
        }
    }
}

// W staging helper (direct, tf32-rounded)
__device__ __forceinline__ void stage_W(float* Ws, const float* __restrict__ W,
                                        int col0) {
    int t = threadIdx.x;
    for (int i4 = t; i4 < 64 * 32; i4 += 256) {
        int cc = i4 >> 5, k4 = i4 & 31;
        float4 v = reinterpret_cast<const float4*>(W + (size_t)(col0 + cc) * 128)[k4];
        v.x = tf32r(v.x); v.y = tf32r(v.y); v.z = tf32r(v.z); v.w = tf32r(v.w);
        *reinterpret_cast<float4*>(Ws + cc * 132 + k4 * 4) = v;
    }
}

// GI/GH with fused m1 gather: y 0..5 -> GI (A=co[idx1]); y 6..11 -> GH (A=hid[idx1])
__global__ void __launch_bounds__(256, 2) k_gemm_g(
        const float* __restrict__ co,  const float* __restrict__ hid,
        const float* __restrict__ Wih, const float* __restrict__ Whh,
        const float* __restrict__ bih, const float* __restrict__ bhh) {
    int y = blockIdx.y;
    const float* A = (y < 6) ? co : hid;
    const float* W = (y < 6) ? Wih : Whh;
    const float* bias = (y < 6) ? bih : bhh;
    float* C = (y < 6) ? g_GI : g_GH;
    int M = g_cnt[0];
    int col0 = (y % 6) * 64;
    int row0 = blockIdx.x * 64;
    if (row0 >= M) return;
    extern __shared__ float sm[];
    int t = threadIdx.x;
    for (int i4 = t; i4 < 64 * 32; i4 += 256) {
        int r = i4 >> 5, k4 = i4 & 31;
        float4 v = make_float4(0.f, 0.f, 0.f, 0.f);
        int s = row0 + r;
        if (s < M) {
            int row = g_idx1[s];
            v = reinterpret_cast<const float4*>(A + (size_t)row * 128)[k4];
        }
        v.x = tf32r(v.x); v.y = tf32r(v.y); v.z = tf32r(v.z); v.w = tf32r(v.w);
        *reinterpret_cast<float4*>(sm + r * 132 + k4 * 4) = v;
    }
    stage_W(sm + 64 * 132, W, col0);
    __syncthreads();
    float c[4][4];
    gemm_mma(sm, c);
    int w = t >> 5, lane = t & 31;
    int g = lane >> 2, tid = lane & 3;
    int mw = w >> 1, nw = w & 1;
    int ra = row0 + 16 * mw + g, rb = ra + 8;
#pragma unroll
    for (int nt = 0; nt < 4; nt++) {
        int cb = col0 + nw * 32 + 8 * nt + 2 * tid;
        float2 bz = *reinterpret_cast<const float2*>(bias + cb);
        if (ra < M)
            *reinterpret_cast<float2*>(C + (size_t)ra * 384 + cb) =
                make_float2(c[nt][0] + bz.x, c[nt][1] + bz.y);
        if (rb < M)
            *reinterpret_cast<float2*>(C + (size_t)rb * 384 + cb) =
                make_float2(c[nt][2] + bz.x, c[nt][3] + bz.y);
    }
}

// QKV with fused m23 gather: y=0 Q (A = no_/un per m2 bit, x 0.125*log2e),
// y=1 K (A=co), y=2,3 V halves (A=co; fp16 transposed output)
__global__ void __launch_bounds__(256, 2) k_gemm_qkv(
        const float* __restrict__ co,  const float* __restrict__ no_,
        const float* __restrict__ un,
        const float* __restrict__ Wq,  const float* __restrict__ bq,
        const float* __restrict__ Wk,  const float* __restrict__ bk,
        const float* __restrict__ Wv,  const float* __restrict__ bv) {
    int y = blockIdx.y;
    const float *W, *bias; int col0;
    if (y == 0)      { W = Wq; bias = bq; col0 = 0; }
    else if (y == 1) { W = Wk; bias = bk; col0 = 0; }
    else             { W = Wv; bias = bv; col0 = (y - 2) * 64; }
    int M = g_cnt[1];
    int row0 = blockIdx.x * 64;
    if (row0 >= M) return;
    extern __shared__ float sm[];
    int t = threadIdx.x;
    for (int i4 = t; i4 < 64 * 32; i4 += 256) {
        int r = i4 >> 5, k4 = i4 & 31;
        float4 v = make_float4(0.f, 0.f, 0.f, 0.f);
        int s = row0 + r;
        if (s < M) {
            int e = g_idx23[s];
            int row = e & 0x3FFFFFFF;
            const float* A = (y == 0) ? ((e & (1 << 30)) ? no_ : un) : co;
            v = reinterpret_cast<const float4*>(A + (size_t)row * 128)[k4];
        }
        v.x = tf32r(v.x); v.y = tf32r(v.y); v.z = tf32r(v.z); v.w = tf32r(v.w);
        *reinterpret_cast<float4*>(sm + r * 132 + k4 * 4) = v;
    }
    stage_W(sm + 64 * 132, W, col0);
    __syncthreads();
    float c[4][4];
    gemm_mma(sm, c);
    int w = t >> 5, lane = t & 31;
    int g = lane >> 2, tid = lane & 3;
    int mw = w >> 1, nw = w & 1;
    int ra = row0 + 16 * mw + g, rb = ra + 8;
    if (y <= 1) {
        __half* dst = (y == 0) ? g_Qh : g_Kh;
        float s = (y == 0) ? 0.18033688011112042f : 1.0f;   // 0.125 * log2(e)
#pragma unroll
        for (int nt = 0; nt < 4; nt++) {
            int cb = nw * 32 + 8 * nt + 2 * tid;
            float2 bz = *reinterpret_cast<const float2*>(bias + cb);
            if (ra < M) {
                __half2 h = __floats2half2_rn((c[nt][0] + bz.x) * s, (c[nt][1] + bz.y) * s);
                *reinterpret_cast<__half2*>(dst + (size_t)ra * 64 + cb) = h;
            }
            if (rb < M) {
                __half2 h = __floats2half2_rn((c[nt][2] + bz.x) * s, (c[nt][3] + bz.y) * s);
                *reinterpret_cast<__half2*>(dst + (size_t)rb * 64 + cb) = h;
            }
        }
    } else {
#pragma unroll
        for (int nt = 0; nt < 4; nt++) {
            int cb = col0 + nw * 32 + 8 * nt + 2 * tid;
            float2 bz = *reinterpret_cast<const float2*>(bias + cb);
            if (ra < M) {
                g_VT[(size_t)cb * CN + ra]       = __float2half(c[nt][0] + bz.x);
                g_VT[(size_t)(cb + 1) * CN + ra] = __float2half(c[nt][1] + bz.y);
            }
            if (rb < M) {
                g_VT[(size_t)cb * CN + rb]       = __float2half(c[nt][2] + bz.x);
                g_VT[(size_t)(cb + 1) * CN + rb] = __float2half(c[nt][3] + bz.y);
            }
        }
    }
}

// ----------------- k_flash: fp16 MMA + ldmatrix + cp.async, no masking -----
// Tail keys: K rows = 0 -> S' = 0 -> ex2 = 1 exactly; V rows = 0 so O is
// unaffected; l over-counts by exactly (#invalid keys), subtracted in epilogue.
#define FLASH_SMEM ((3 * 64 * 72 + 2 * 128 * 72) * 2)
__global__ void __launch_bounds__(128, 3) k_flash() {
    int n23 = g_cnt[1];
    int qb = blockIdx.x / KSPLIT;
    int sp = blockIdx.x % KSPLIT;
    int q0 = qb * 64;
    if (q0 >= n23) return;
    extern __shared__ __half smh[];
    __half* Qs = smh;                              // [64][72]
    int t = threadIdx.x;
    int w = t >> 5, lane = t & 31;
    int g = lane >> 2, tid = lane & 3;
    unsigned lofs = (unsigned)(((lane & 7) * 72 + 8 * (lane >> 3)) * 2);

    int nkb = (n23 + 63) >> 6;
    int chunk = (nkb + KSPLIT - 1) / KSPLIT;
    int kb0 = sp * chunk;
    int kb1 = min(kb0 + chunk, nkb);

    // issue async loads for first K/V tile (stage 0) before staging Q
    {
        int k0 = kb0 << 6;
        __half* Kst = smh + 64 * 72;
        __half* Vst = smh + 3 * 64 * 72;
        for (int i = t; i < 64 * 8; i += 128) {
            int r = i >> 3, c8 = i & 7;
            cp16((unsigned)__cvta_generic_to_shared(Kst + r * 72 + 8 * c8),
                 g_Kh + (size_t)(k0 + r) * AT + 8 * c8);
        }
        for (int i = t; i < 128 * 8; i += 128) {
            int d = i >> 3, j8 = i & 7;
            cp16((unsigned)__cvta_generic_to_shared(Vst + d * 72 + 8 * j8),
                 g_VT + (size_t)d * CN + k0 + 8 * j8);
        }
        asm volatile("cp.async.commit_group;");
    }
    // stage Q tile (overlaps with the async loads above)
    for (int i = t; i < 64 * 8; i += 128) {
        int r = i >> 3, c8 = i & 7;
        *reinterpret_cast<uint4*>(Qs + r * 72 + 8 * c8) =
            *reinterpret_cast<const uint4*>(g_Qh + (size_t)(q0 + r) * AT + 8 * c8);
    }
    __syncthreads();
    // preload Q A-fragments (4 k-chunks of 16)
    unsigned qa[4][4];
    {
        const __half* r0 = Qs + (16 * w + g) * 72;
        const __half* r8 = Qs + (16 * w + g + 8) * 72;
#pragma unroll
        for (int ks = 0; ks < 4; ks++) {
            qa[ks][0] = *reinterpret_cast<const unsigned*>(r0 + 16 * ks + 2 * tid);
            qa[ks][1] = *reinterpret_cast<const unsigned*>(r8 + 16 * ks + 2 * tid);
            qa[ks][2] = *reinterpret_cast<const unsigned*>(r0 + 16 * ks + 2 * tid + 8);
            qa[ks][3] = *reinterpret_cast<const unsigned*>(r8 + 16 * ks + 2 * tid + 8);
        }
    }
    float o[16][4];
#pragma unroll
    for (int nt = 0; nt < 16; nt++)
#pragma unroll
        for (int i = 0; i < 4; i++) o[nt][i] = 0.f;
    float l0 = 0.f, l1 = 0.f;

    for (int kb = kb0; kb < kb1; kb++) {
        int st = (kb - kb0) & 1;
        bool has_next = (kb + 1 < kb1);
        if (has_next) {
            int k0n = (kb + 1) << 6;
            int sn = st ^ 1;
            __half* Kst = smh + (1 + sn) * 64 * 72;
            __half* Vst = smh + 3 * 64 * 72 + sn * 128 * 72;
            for (int i = t; i < 64 * 8; i += 128) {
                int r = i >> 3, c8 = i & 7;
                cp16((unsigned)__cvta_generic_to_shared(Kst + r * 72 + 8 * c8),
                     g_Kh + (size_t)(k0n + r) * AT + 8 * c8);
            }
            for (int i = t; i < 128 * 8; i += 128) {
                int d = i >> 3, j8 = i & 7;
                cp16((unsigned)__cvta_generic_to_shared(Vst + d * 72 + 8 * j8),
                     g_VT + (size_t)d * CN + k0n + 8 * j8);
            }
            asm volatile("cp.async.commit_group;");
            asm volatile("cp.async.wait_group 1;");
        } else {
            asm volatile("cp.async.wait_group 0;");
        }
        __syncthreads();
        unsigned KsA = (unsigned)__cvta_generic_to_shared(smh + (1 + st) * 64 * 72) + lofs;
        unsigned VtA = (unsigned)__cvta_generic_to_shared(smh + 3 * 64 * 72 + st * 128 * 72) + lofs;
        // S = Q K^T : 8 key-tiles, B-fragments via 2 ldmatrix.x4 each
        float c[8][4];
#pragma unroll
        for (int nt = 0; nt < 8; nt++)
#pragma unroll
            for (int i = 0; i < 4; i++) c[nt][i] = 0.f;
#pragma unroll
        for (int nt = 0; nt < 8; nt++) {
            unsigned base = KsA + nt * (8 * 72 * 2);
            unsigned b0, b1, b2, b3;
            ldsm4(b0, b1, b2, b3, base);
            mma_f16(c[nt], qa[0], b0, b1);
            mma_f16(c[nt], qa[1], b2, b3);
            ldsm4(b0, b1, b2, b3, base + 64);
            mma_f16(c[nt], qa[2], b0, b1);
            mma_f16(c[nt], qa[3], b2, b3);
        }
        // P = 2^S' (log2e pre-folded), unmasked; invalid keys give exactly 1
        unsigned pa[4][4];
#pragma unroll
        for (int nt = 0; nt < 8; nt++) {
            float p0 = ex2(c[nt][0]);
            float p1 = ex2(c[nt][1]);
            float p2 = ex2(c[nt][2]);
            float p3 = ex2(c[nt][3]);
            l0 += p0 + p1;
            l1 += p2 + p3;
            int kc = nt >> 1, h = (nt & 1) * 2;
            pa[kc][h]     = pack_h2(p0, p1);
            pa[kc][h + 1] = pack_h2(p2, p3);
        }
        // O += P V : 16 d-tiles, B-fragments via 2 ldmatrix.x4 each
#pragma unroll
        for (int nt = 0; nt < 16; nt++) {
            unsigned base = VtA + nt * (8 * 72 * 2);
            unsigned b0, b1, b2, b3;
            ldsm4(b0, b1, b2, b3, base);
            mma_f16(o[nt], pa[0], b0, b1);
            mma_f16(o[nt], pa[1], b2, b3);
            ldsm4(b0, b1, b2, b3, base + 64);
            mma_f16(o[nt], pa[2], b0, b1);
            mma_f16(o[nt], pa[3], b2, b3);
        }
        __syncthreads();   // all reads of stage st done before its next refill
    }
    // ---- epilogue ----
    int inv = kb1 * 64 - max(n23, kb0 * 64);
    if (inv < 0) inv = 0;
    l0 += __shfl_xor_sync(0xffffffffu, l0, 1);
    l0 += __shfl_xor_sync(0xffffffffu, l0, 2);
    l1 += __shfl_xor_sync(0xffffffffu, l1, 1);
    l1 += __shfl_xor_sync(0xffffffffu, l1, 2);
    float* lr = reinterpret_cast<float*>(Qs);   // Qs no longer needed
    if (tid == 0) {
        lr[16 * w + g] = l0 - (float)inv;
        lr[16 * w + g + 8] = l1 - (float)inv;
    }
    __syncthreads();
    if (t < 64 && q0 + t < n23)
        g_L3[sp * CN + q0 + t] = lr[t];
    int r0 = q0 + 16 * w + g;
    int r8 = r0 + 8;
    float* base0 = g_O3 + ((size_t)sp * CN + r0) * 128 + 2 * tid;
    float* base8 = g_O3 + ((size_t)sp * CN + r8) * 128 + 2 * tid;
#pragma unroll
    for (int nt = 0; nt < 16; nt++) {
        if (r0 < n23)
            *reinterpret_cast<float2*>(base0 + 8 * nt) = make_float2(o[nt][0], o[nt][1]);
        if (r8 < n23)
            *reinterpret_cast<float2*>(base8 + 8 * nt) = make_float2(o[nt][2], o[nt][3]);
    }
}

// ----------------- k_combine: split-combine + scatter + max (main) ---------
__global__ void k_combine(float* __restrict__ outH) {
    int t = threadIdx.x;
    int c = t & 127, sub = t >> 7;
    float mx = -FLT_MAX;
    int n23 = g_cnt[1];
    int s0 = blockIdx.x * 8;
#pragma unroll
    for (int k = 0; k < 4; k++) {
        int sl = s0 + sub * 4 + k;
        if (sl < n23) {
            float lt = 0.f, ov = 0.f;
#pragma unroll
            for (int sp = 0; sp < KSPLIT; sp++) {
                lt += g_L3[sp * CN + sl];
                ov += g_O3[((size_t)sp * CN + sl) * 128 + c];
            }
            float h = tanhf(ov / lt);
            int row = g_idx23[sl] & 0x3FFFFFFF;
            outH[(size_t)row * 128 + c] = h;
            mx = fmaxf(mx, h);
        }
    }
    __shared__ float red[2][128];
    red[sub][c] = mx;
    __syncthreads();
    if (t < 128) atomicMax(&g_outacc[t], ford(fmaxf(red[0][t], red[1][t])));
}

// ----------------- k_gruc: GRU gates + scatter + max (side) ----------------
__global__ void k_gruc(const float* __restrict__ hid, float* __restrict__ outH) {
    int t = threadIdx.x;
    int c = t & 127, sub = t >> 7;
    float mx = -FLT_MAX;
    int n1 = g_cnt[0];
    int s0 = blockIdx.x * 8;
#pragma unroll
    for (int k = 0; k < 4; k++) {
        int s = s0 + sub * 4 + k;
        if (s < n1) {
            int row = g_idx1[s];
            const float* gi = g_GI + (size_t)s * 384;
            const float* gh = g_GH + (size_t)s * 384;
            float r  = 1.f / (1.f + __expf(-(gi[c] + gh[c])));
            float z  = 1.f / (1.f + __expf(-(gi[128 + c] + gh[128 + c])));
            float nn = tanhf(gi[256 + c] + r * gh[256 + c]);
            float h  = hid[(size_t)row * 128 + c];
            float o  = (1.f - z) * nn + z * h;
            outH[(size_t)row * 128 + c] = o;
            mx = fmaxf(mx, o);
        }
    }
    __shared__ float red[2][128];
    red[sub][c] = mx;
    __syncthreads();
    if (t < 128) atomicMax(&g_outacc[t], ford(fmaxf(red[0][t], red[1][t])));
}

// ----------------- k_final: output vector + reset counters for next run ----
__global__ void k_final(float* __restrict__ out) {
    int t = threadIdx.x;
    out[t] = funord(g_outacc[t]) + g_tf[t];
    if (t == 0) { g_cnt[0] = 0; g_cnt[1] = 0; }
}

// ---------------------------------------------------------------------------
extern "C" void kernel_launch(void* const* d_in, const int* in_sizes, int n_in,
                              void* d_out, int out_size) {
    const float* interval = (const float*)d_in[0];
    const float* co   = (const float*)d_in[1];
    const float* no_  = (const float*)d_in[2];
    const float* un   = (const float*)d_in[3];
    const float* hid  = (const float*)d_in[4];
    const int*   divided = (const int*)d_in[5];
    const float* W_ih = (const float*)d_in[6];
    const float* W_hh = (const float*)d_in[7];
    const float* b_ih = (const float*)d_in[8];
    const float* b_hh = (const float*)d_in[9];
    const float* Wq = (const float*)d_in[10];
    const float* bq = (const float*)d_in[11];
    const float* Wk = (const float*)d_in[12];
    const float* bk = (const float*)d_in[13];
    const float* Wv = (const float*)d_in[14];
    const float* bv = (const float*)d_in[15];
    const float* Wt = (const float*)d_in[16];
    const float* bt = (const float*)d_in[17];
    float* out  = (float*)d_out;
    float* outH = out + HD;   // h_new region: [12288, 128] after the 128-vec

    // side stream + fork/join events (created once; identical work every call)
    static cudaStream_t s2 = nullptr;
    static cudaEvent_t e0 = nullptr, e1 = nullptr, e2 = nullptr, e3 = nullptr;
    if (s2 == nullptr) {
        cudaStreamCreateWithFlags(&s2, cudaStreamNonBlocking);
        cudaEventCreateWithFlags(&e0, cudaEventDisableTiming);
        cudaEventCreateWithFlags(&e1, cudaEventDisableTiming);
        cudaEventCreateWithFlags(&e2, cudaEventDisableTiming);
        cudaEventCreateWithFlags(&e3, cudaEventDisableTiming);
    }

    cudaFuncSetAttribute(k_gemm_g,   cudaFuncAttributeMaxDynamicSharedMemorySize, GEMM_SMEM);
    cudaFuncSetAttribute(k_gemm_qkv, cudaFuncAttributeMaxDynamicSharedMemorySize, GEMM_SMEM);
    cudaFuncSetAttribute(k_flash,    cudaFuncAttributeMaxDynamicSharedMemorySize, FLASH_SMEM);

    // fork at top: side stream zeroes outH immediately
    cudaEventRecord(e0, 0);
    cudaStreamWaitEvent(s2, e0, 0);
    k_zero<<<768, 512, 0, s2>>>(outH);

    // main: compact, then m23 pipeline (gathers fused into GEMM staging)
    k_initA<<<24, 512>>>(interval, Wt, bt, divided);
    cudaEventRecord(e1, 0);

    // side: after compact -> GI/GH GEMM (fused m1 gather), GRU
    cudaStreamWaitEvent(s2, e1, 0);
    k_gemm_g<<<dim3(192, 12), 256, GEMM_SMEM, s2>>>(co, hid, W_ih, W_hh, b_ih, b_hh);
    cudaEventRecord(e2, s2);         // zero + m1-gemm done (combine may write outH)
    k_gruc<<<CN / 8, 256, 0, s2>>>(hid, outH);
    cudaEventRecord(e3, s2);         // gruc done (final may read outacc)

    k_gemm_qkv<<<dim3(192, 4), 256, GEMM_SMEM>>>(co, no_, un,
                                                 Wq, bq, Wk, bk, Wv, bv);
    k_flash<<<(CN / 64) * KSPLIT, 128, FLASH_SMEM>>>();

    cudaStreamWaitEvent(0, e2, 0);   // outH zero complete before combine writes
    k_combine<<<CN / 8, 256>>>(outH);
    cudaStreamWaitEvent(0, e3, 0);
    k_final<<<1, 128>>>(out);
}